// round 1
// baseline (speedup 1.0000x reference)
#include <cuda_runtime.h>
#include <math.h>

#define NLAYERS 4
#define NHEADS  16
#define DMODEL  1024
#define DFF     4096
#define KW      7
#define SEQ     2048
#define CIN     4
#define COUT    4
#define HD      64

// ---------------- scratch (device globals; no allocation allowed) ----------------
__device__ float g_x [SEQ*DMODEL];
__device__ float g_hn[SEQ*DMODEL];
__device__ float g_q [SEQ*DMODEL];
__device__ float g_k [SEQ*DMODEL];
__device__ float g_v [SEQ*DMODEL];
__device__ float g_o [SEQ*DMODEL];
__device__ float g_h1[SEQ*DFF];
__device__ float g_h2[SEQ*DFF];

// ---------------- conv_in: h[l][d] = relu(b[d] + sum_{c,t} w[d,c,t]*x[c, l+t-6]) ----
__global__ void conv_in_kernel(const float* __restrict__ x,
                               const float* __restrict__ w,
                               const float* __restrict__ b,
                               float* __restrict__ h)
{
    int idx = blockIdx.x * blockDim.x + threadIdx.x;
    if (idx >= SEQ * DMODEL) return;
    int d = idx & (DMODEL - 1);
    int l = idx >> 10;
    float acc = b[d];
#pragma unroll
    for (int c = 0; c < CIN; ++c) {
#pragma unroll
        for (int t = 0; t < KW; ++t) {
            int lt = l + t - (KW - 1);
            if (lt >= 0) acc += w[(d * CIN + c) * KW + t] * x[c * SEQ + lt];
        }
    }
    h[idx] = fmaxf(acc, 0.0f);
}

// ---------------- conv_out: out[co][l] = b[co] + sum_{d,t} w[co,d,t]*X[l+t-6][d] ----
__global__ void conv_out_kernel(const float* __restrict__ xb,
                                const float* __restrict__ w,
                                const float* __restrict__ b,
                                float* __restrict__ out)
{
    int l  = blockIdx.x;
    int co = blockIdx.y;
    float acc = 0.0f;
    for (int d = threadIdx.x; d < DMODEL; d += 128) {
        const float* wp = w + (size_t)(co * DMODEL + d) * KW;
#pragma unroll
        for (int t = 0; t < KW; ++t) {
            int lt = l + t - (KW - 1);
            if (lt >= 0) acc += wp[t] * xb[(size_t)lt * DMODEL + d];
        }
    }
#pragma unroll
    for (int s = 16; s >= 1; s >>= 1) acc += __shfl_xor_sync(0xffffffffu, acc, s);
    __shared__ float red[4];
    if ((threadIdx.x & 31) == 0) red[threadIdx.x >> 5] = acc;
    __syncthreads();
    if (threadIdx.x == 0)
        out[co * SEQ + l] = red[0] + red[1] + red[2] + red[3] + b[co];
}

// ---------------- RMSNorm per row of 1024 -----------------------------------------
__global__ void __launch_bounds__(256) rmsnorm_kernel(const float* __restrict__ x,
                                                      const float* __restrict__ w,
                                                      const float* __restrict__ b,
                                                      float* __restrict__ y)
{
    int l = blockIdx.x;
    const float* xr = x + (size_t)l * DMODEL;
    float ss = 0.0f;
    for (int i = threadIdx.x; i < DMODEL; i += 256) { float v = xr[i]; ss += v * v; }
#pragma unroll
    for (int s = 16; s >= 1; s >>= 1) ss += __shfl_xor_sync(0xffffffffu, ss, s);
    __shared__ float red[8];
    __shared__ float sinv;
    if ((threadIdx.x & 31) == 0) red[threadIdx.x >> 5] = ss;
    __syncthreads();
    if (threadIdx.x == 0) {
        float t = 0.0f;
#pragma unroll
        for (int i = 0; i < 8; ++i) t += red[i];
        sinv = rsqrtf(t * (1.0f / DMODEL) + 1e-5f);
    }
    __syncthreads();
    float inv = sinv;
    float* yr = y + (size_t)l * DMODEL;
    for (int i = threadIdx.x; i < DMODEL; i += 256)
        yr[i] = xr[i] * inv * w[i] + b[i];
}

// ---------------- RoPE (NeoX rotate-half) on q and k in place ----------------------
__global__ void rope_kernel(float* __restrict__ q, float* __restrict__ k)
{
    int idx = blockIdx.x * blockDim.x + threadIdx.x;
    if (idx >= SEQ * NHEADS * (HD / 2)) return;
    int j = idx & 31;
    int h = (idx >> 5) & (NHEADS - 1);
    int l = idx >> 9;
    // inv_freq = 10000^(-j/32) = 2^(-j * log2(10000)/32)
    float inv_freq = exp2f(-(float)j * (13.287712379549449f / 32.0f));
    float ang = (float)l * inv_freq;
    float s, c;
    sincosf(ang, &s, &c);
    int base = l * DMODEL + h * HD + j;
    float q1 = q[base], q2 = q[base + 32];
    q[base]      = q1 * c - q2 * s;
    q[base + 32] = q2 * c + q1 * s;
    float k1 = k[base], k2 = k[base + 32];
    k[base]      = k1 * c - k2 * s;
    k[base + 32] = k2 * c + k1 * s;
}

// ---------------- GEMM: C[M,N] = op(A[M,K] @ B[N,K]^T (+bias) (relu)) (+res) -------
// 128x128x8 tile, 256 threads, 8x8 per-thread register tile.
template<bool BIAS, bool RELU, bool RES>
__global__ void __launch_bounds__(256, 2)
gemm_nt(int M, int N, int K,
        const float* __restrict__ A, const float* __restrict__ B,
        const float* __restrict__ bias, const float* __restrict__ res,
        float* __restrict__ C)
{
    __shared__ float As[8][128];
    __shared__ float Bs[8][128];
    const int tid = threadIdx.x;
    const int tx  = tid & 15;
    const int ty  = tid >> 4;
    const int m0  = blockIdx.y * 128;
    const int n0  = blockIdx.x * 128;

    const int lr = tid >> 1;          // 0..127
    const int lc = (tid & 1) << 2;    // 0 or 4

    const float* Ap = A + (size_t)(m0 + lr) * K + lc;
    const float* Bp = B + (size_t)(n0 + lr) * K + lc;

    float acc[8][8];
#pragma unroll
    for (int i = 0; i < 8; ++i)
#pragma unroll
        for (int j = 0; j < 8; ++j) acc[i][j] = 0.0f;

    for (int k0 = 0; k0 < K; k0 += 8) {
        float4 av = *(const float4*)(Ap + k0);
        float4 bv = *(const float4*)(Bp + k0);
        __syncthreads();
        As[lc + 0][lr] = av.x; As[lc + 1][lr] = av.y;
        As[lc + 2][lr] = av.z; As[lc + 3][lr] = av.w;
        Bs[lc + 0][lr] = bv.x; Bs[lc + 1][lr] = bv.y;
        Bs[lc + 2][lr] = bv.z; Bs[lc + 3][lr] = bv.w;
        __syncthreads();
#pragma unroll
        for (int kk = 0; kk < 8; ++kk) {
            float a[8], b0[4], b1[4];
#pragma unroll
            for (int i = 0; i < 8; ++i) a[i] = As[kk][ty * 8 + i];
#pragma unroll
            for (int j = 0; j < 4; ++j) {
                b0[j] = Bs[kk][tx * 4 + j];
                b1[j] = Bs[kk][64 + tx * 4 + j];
            }
#pragma unroll
            for (int i = 0; i < 8; ++i) {
#pragma unroll
                for (int j = 0; j < 4; ++j) {
                    acc[i][j]     += a[i] * b0[j];
                    acc[i][j + 4] += a[i] * b1[j];
                }
            }
        }
    }
    // epilogue: two float4 column chunks per row
#pragma unroll
    for (int half = 0; half < 2; ++half) {
        int n = n0 + half * 64 + tx * 4;
        float4 bb = make_float4(0.f, 0.f, 0.f, 0.f);
        if (BIAS) bb = *(const float4*)(bias + n);
#pragma unroll
        for (int i = 0; i < 8; ++i) {
            int m = m0 + ty * 8 + i;
            float4 v;
            v.x = acc[i][half * 4 + 0];
            v.y = acc[i][half * 4 + 1];
            v.z = acc[i][half * 4 + 2];
            v.w = acc[i][half * 4 + 3];
            if (BIAS) { v.x += bb.x; v.y += bb.y; v.z += bb.z; v.w += bb.w; }
            if (RELU) {
                v.x = fmaxf(v.x, 0.f); v.y = fmaxf(v.y, 0.f);
                v.z = fmaxf(v.z, 0.f); v.w = fmaxf(v.w, 0.f);
            }
            if (RES) {
                float4 r = *(const float4*)(res + (size_t)m * N + n);
                v.x += r.x; v.y += r.y; v.z += r.z; v.w += r.w;
            }
            *(float4*)(C + (size_t)m * N + n) = v;
        }
    }
}

// ---------------- Flash attention, 64x64 tiles, online softmax ---------------------
#define ATTN_PAD 65
#define ATTN_SMEM (4 * 64 * ATTN_PAD * (int)sizeof(float))

__global__ void __launch_bounds__(256) attn_kernel(const float* __restrict__ Q,
                                                   const float* __restrict__ Kt,
                                                   const float* __restrict__ V,
                                                   float* __restrict__ O)
{
    extern __shared__ float sm[];
    float* Qs = sm;
    float* Ks = sm + 64 * ATTN_PAD;
    float* Vs = sm + 2 * 64 * ATTN_PAD;
    float* Ps = sm + 3 * 64 * ATTN_PAD;

    const int h  = blockIdx.y;
    const int qt = blockIdx.x;
    const int q0 = qt * 64;
    const int tid = threadIdx.x;
    const int tx = tid & 15;   // 16 column groups of 4
    const int ty = tid >> 4;   // 16 row groups of 4

    for (int i = tid; i < 64 * 64; i += 256) {
        int r = i >> 6, c = i & 63;
        Qs[r * ATTN_PAD + c] = Q[(size_t)(q0 + r) * DMODEL + h * HD + c];
    }

    float m_i[4], l_i[4], oacc[4][4];
#pragma unroll
    for (int r = 0; r < 4; ++r) {
        m_i[r] = -INFINITY; l_i[r] = 0.0f;
#pragma unroll
        for (int c = 0; c < 4; ++c) oacc[r][c] = 0.0f;
    }

    for (int jt = 0; jt <= qt; ++jt) {
        const int k0 = jt * 64;
        __syncthreads();
        for (int i = tid; i < 64 * 64; i += 256) {
            int r = i >> 6, c = i & 63;
            Ks[r * ATTN_PAD + c] = Kt[(size_t)(k0 + r) * DMODEL + h * HD + c];
            Vs[r * ATTN_PAD + c] = V [(size_t)(k0 + r) * DMODEL + h * HD + c];
        }
        __syncthreads();

        float s[4][4];
#pragma unroll
        for (int r = 0; r < 4; ++r)
#pragma unroll
            for (int c = 0; c < 4; ++c) s[r][c] = 0.0f;

        for (int d = 0; d < HD; ++d) {
            float qv[4], kv[4];
#pragma unroll
            for (int r = 0; r < 4; ++r) qv[r] = Qs[(ty * 4 + r) * ATTN_PAD + d];
#pragma unroll
            for (int c = 0; c < 4; ++c) kv[c] = Ks[(tx * 4 + c) * ATTN_PAD + d];
#pragma unroll
            for (int r = 0; r < 4; ++r)
#pragma unroll
                for (int c = 0; c < 4; ++c) s[r][c] += qv[r] * kv[c];
        }

        const bool diag = (jt == qt);
#pragma unroll
        for (int r = 0; r < 4; ++r) {
            const int qi = q0 + ty * 4 + r;
            float rowmax = -INFINITY;
#pragma unroll
            for (int c = 0; c < 4; ++c) {
                s[r][c] *= 0.125f;  // 1/sqrt(HD)
                if (diag) { int ki = k0 + tx * 4 + c; if (ki > qi) s[r][c] = -INFINITY; }
                rowmax = fmaxf(rowmax, s[r][c]);
            }
#pragma unroll
            for (int w = 8; w >= 1; w >>= 1)
                rowmax = fmaxf(rowmax, __shfl_xor_sync(0xffffffffu, rowmax, w));
            float mnew  = fmaxf(m_i[r], rowmax);
            float alpha = expf(m_i[r] - mnew);
            m_i[r] = mnew;
            float rsum = 0.0f;
#pragma unroll
            for (int c = 0; c < 4; ++c) {
                float p = expf(s[r][c] - mnew);
                s[r][c] = p;
                rsum += p;
            }
#pragma unroll
            for (int w = 8; w >= 1; w >>= 1)
                rsum += __shfl_xor_sync(0xffffffffu, rsum, w);
            l_i[r] = l_i[r] * alpha + rsum;
#pragma unroll
            for (int c = 0; c < 4; ++c) {
                oacc[r][c] *= alpha;
                Ps[(ty * 4 + r) * ATTN_PAD + tx * 4 + c] = s[r][c];
            }
        }
        __syncthreads();

        for (int j = 0; j < 64; ++j) {
            float pv[4], vv[4];
#pragma unroll
            for (int r = 0; r < 4; ++r) pv[r] = Ps[(ty * 4 + r) * ATTN_PAD + j];
#pragma unroll
            for (int c = 0; c < 4; ++c) vv[c] = Vs[j * ATTN_PAD + tx * 4 + c];
#pragma unroll
            for (int r = 0; r < 4; ++r)
#pragma unroll
                for (int c = 0; c < 4; ++c) oacc[r][c] += pv[r] * vv[c];
        }
    }

#pragma unroll
    for (int r = 0; r < 4; ++r) {
        float invl = 1.0f / l_i[r];
#pragma unroll
        for (int c = 0; c < 4; ++c)
            O[(size_t)(q0 + ty * 4 + r) * DMODEL + h * HD + tx * 4 + c] = oacc[r][c] * invl;
    }
}

// ---------------- host launcher ----------------------------------------------------
extern "C" void kernel_launch(void* const* d_in, const int* in_sizes, int n_in,
                              void* d_out, int out_size)
{
    const float* x_in       = (const float*)d_in[0];
    const float* conv_in_w  = (const float*)d_in[1];
    const float* conv_in_b  = (const float*)d_in[2];
    const float* ln1_w      = (const float*)d_in[3];
    const float* ln1_b      = (const float*)d_in[4];
    const float* wq         = (const float*)d_in[5];
    const float* wk         = (const float*)d_in[6];
    const float* wv         = (const float*)d_in[7];
    const float* wo         = (const float*)d_in[8];
    const float* ln2_w      = (const float*)d_in[9];
    const float* ln2_b      = (const float*)d_in[10];
    const float* w1         = (const float*)d_in[11];
    const float* b1         = (const float*)d_in[12];
    const float* w2         = (const float*)d_in[13];
    const float* b2         = (const float*)d_in[14];
    const float* w3         = (const float*)d_in[15];
    const float* b3         = (const float*)d_in[16];
    const float* conv_out_w = (const float*)d_in[17];
    const float* conv_out_b = (const float*)d_in[18];
    float* out = (float*)d_out;

    float *px, *phn, *pq, *pk, *pv, *po, *ph1, *ph2;
    cudaGetSymbolAddress((void**)&px,  g_x);
    cudaGetSymbolAddress((void**)&phn, g_hn);
    cudaGetSymbolAddress((void**)&pq,  g_q);
    cudaGetSymbolAddress((void**)&pk,  g_k);
    cudaGetSymbolAddress((void**)&pv,  g_v);
    cudaGetSymbolAddress((void**)&po,  g_o);
    cudaGetSymbolAddress((void**)&ph1, g_h1);
    cudaGetSymbolAddress((void**)&ph2, g_h2);

    cudaFuncSetAttribute(attn_kernel, cudaFuncAttributeMaxDynamicSharedMemorySize, ATTN_SMEM);

    conv_in_kernel<<<(SEQ * DMODEL) / 256, 256>>>(x_in, conv_in_w, conv_in_b, px);

    const dim3 gD(DMODEL / 128, SEQ / 128);   // N=1024 GEMMs
    const dim3 gF(DFF / 128,    SEQ / 128);   // N=4096 GEMMs

    for (int i = 0; i < NLAYERS; ++i) {
        rmsnorm_kernel<<<SEQ, 256>>>(px, ln1_w + i * DMODEL, ln1_b + i * DMODEL, phn);

        gemm_nt<false, false, false><<<gD, 256>>>(SEQ, DMODEL, DMODEL, phn,
            wq + (size_t)i * DMODEL * DMODEL, nullptr, nullptr, pq);
        gemm_nt<false, false, false><<<gD, 256>>>(SEQ, DMODEL, DMODEL, phn,
            wk + (size_t)i * DMODEL * DMODEL, nullptr, nullptr, pk);
        gemm_nt<false, false, false><<<gD, 256>>>(SEQ, DMODEL, DMODEL, phn,
            wv + (size_t)i * DMODEL * DMODEL, nullptr, nullptr, pv);

        rope_kernel<<<(SEQ * NHEADS * (HD / 2)) / 256, 256>>>(pq, pk);

        attn_kernel<<<dim3(SEQ / 64, NHEADS), 256, ATTN_SMEM>>>(pq, pk, pv, po);

        gemm_nt<false, false, true><<<gD, 256>>>(SEQ, DMODEL, DMODEL, po,
            wo + (size_t)i * DMODEL * DMODEL, nullptr, px, px);

        rmsnorm_kernel<<<SEQ, 256>>>(px, ln2_w + i * DMODEL, ln2_b + i * DMODEL, phn);

        gemm_nt<true, true, false><<<gF, 256>>>(SEQ, DFF, DMODEL, phn,
            w1 + (size_t)i * DFF * DMODEL, b1 + (size_t)i * DFF, nullptr, ph1);
        gemm_nt<true, true, false><<<gF, 256>>>(SEQ, DFF, DFF, ph1,
            w2 + (size_t)i * DFF * DFF, b2 + (size_t)i * DFF, nullptr, ph2);
        gemm_nt<true, false, true><<<gD, 256>>>(SEQ, DMODEL, DFF, ph2,
            w3 + (size_t)i * DMODEL * DFF, b3 + (size_t)i * DMODEL, px, px);
    }

    conv_out_kernel<<<dim3(SEQ, COUT), 128>>>(px, conv_out_w, conv_out_b, out);
}

// round 4
// speedup vs baseline: 2.1512x; 2.1512x over previous
#include <cuda_runtime.h>
#include <cuda_bf16.h>
#include <math.h>
#include <cstdint>

#define NLAYERS 4
#define NHEADS  16
#define DMODEL  1024
#define DFF     4096
#define KW      7
#define SEQ     2048
#define CIN     4
#define COUT    4
#define HD      64

// ---------------- scratch (device globals; no allocation allowed) ----------------
__device__ float g_x [SEQ*DMODEL];
__device__ float g_hn[SEQ*DMODEL];
__device__ float g_q [SEQ*DMODEL];
__device__ float g_k [SEQ*DMODEL];
__device__ float g_v [SEQ*DMODEL];
__device__ float g_o [SEQ*DMODEL];
__device__ float g_h1[SEQ*DFF];
__device__ float g_h2[SEQ*DFF];

__device__ __forceinline__ uint32_t smem_u32(const void* p) {
    uint32_t a;
    asm("{ .reg .u64 t; cvta.to.shared.u64 t, %1; cvt.u32.u64 %0, t; }" : "=r"(a) : "l"(p));
    return a;
}

// ================= HMMA bf16 GEMM: C[M,N] = op(A[M,K] @ B[N,K]^T) =================
// 3-term compensated bf16 product: Ah*Bh + Al*Bh + Ah*Bl (fp32 accum).
// CTA tile 128x128, 8 warps (2x4), warp tile 64x32, K-chunk 32, double-buffered.

#define GSTRIDE 80                 // padded row stride in bytes (32 bf16 + 8 pad)
#define AH_OFF 0
#define AL_OFF 10240
#define BH_OFF 20480
#define BL_OFF 30720
#define STAGE_SZ 40960
#define GSMEM_TOTAL (2 * STAGE_SZ)

__device__ __forceinline__ void ldm4(uint32_t addr, uint32_t& r0, uint32_t& r1,
                                     uint32_t& r2, uint32_t& r3) {
    asm volatile("ldmatrix.sync.aligned.m8n8.x4.shared.b16 {%0,%1,%2,%3}, [%4];"
                 : "=r"(r0), "=r"(r1), "=r"(r2), "=r"(r3) : "r"(addr));
}
__device__ __forceinline__ void mma16816(float* c, const uint32_t* a, const uint32_t* b) {
    asm volatile(
        "mma.sync.aligned.m16n8k16.row.col.f32.bf16.bf16.f32 "
        "{%0,%1,%2,%3}, {%4,%5,%6,%7}, {%8,%9}, {%0,%1,%2,%3};"
        : "+f"(c[0]), "+f"(c[1]), "+f"(c[2]), "+f"(c[3])
        : "r"(a[0]), "r"(a[1]), "r"(a[2]), "r"(a[3]), "r"(b[0]), "r"(b[1]));
}

__device__ __forceinline__ void split2(float x, float y, uint32_t& hi, uint32_t& lo) {
    __nv_bfloat16 hx = __float2bfloat16(x), hy = __float2bfloat16(y);
    __nv_bfloat16 lx = __float2bfloat16(x - __bfloat162float(hx));
    __nv_bfloat16 ly = __float2bfloat16(y - __bfloat162float(hy));
    hi = (uint32_t)__bfloat16_as_ushort(hx) | ((uint32_t)__bfloat16_as_ushort(hy) << 16);
    lo = (uint32_t)__bfloat16_as_ushort(lx) | ((uint32_t)__bfloat16_as_ushort(ly) << 16);
}

template<bool BIAS, bool RELU, bool RES>
__global__ void __launch_bounds__(256)
gemm_mma(int K, int N,
         const float* __restrict__ A, const float* __restrict__ B,
         const float* __restrict__ bias, const float* __restrict__ res,
         float* __restrict__ C)
{
    extern __shared__ __align__(128) char smem[];
    const uint32_t sb = smem_u32(smem);
    const int tid  = threadIdx.x;
    const int wid  = tid >> 5;
    const int lane = tid & 31;
    const int wm   = wid >> 2;       // 0..1  (64 rows each)
    const int wn   = wid & 3;        // 0..3  (32 cols each)
    const int m0   = blockIdx.y * 128;
    const int n0   = blockIdx.x * 128;

    float acc[4][4][4];
#pragma unroll
    for (int i = 0; i < 4; ++i)
#pragma unroll
        for (int j = 0; j < 4; ++j)
#pragma unroll
            for (int q = 0; q < 4; ++q) acc[i][j][q] = 0.0f;

    // loader mapping: flat float4 index fl in [0,1024): row = fl>>3, quad = fl&7
    const int lrow = tid >> 3;       // base row for t=0 (rows advance by 32 per t)
    const int lq   = tid & 7;

    const float* Abase = A + (size_t)(m0 + lrow) * K + lq * 4;
    const float* Bbase = B + (size_t)(n0 + lrow) * K + lq * 4;
    const int rowstep = 32;          // rows per t-iteration

    const int nchunk = K >> 5;

    // lane addressing for ldmatrix
    const int sub = lane >> 3, r8 = lane & 7;
    // A: row = base + (sub&1)*8 + r8 ; kcol = (sub>>1)*8
    const uint32_t a_lane_off = (uint32_t)(((sub & 1) * 8 + r8) * GSTRIDE + ((sub >> 1) * 8) * 2);
    // B: n = base + (sub>>1)*8 + r8 ; kcol = (sub&1)*8
    const uint32_t b_lane_off = (uint32_t)((((sub >> 1) * 8) + r8) * GSTRIDE + ((sub & 1) * 8) * 2);

    // ---- prologue: load chunk 0 into stage 0 ----
    {
        char* stg = smem;
#pragma unroll
        for (int t = 0; t < 4; ++t) {
            float4 av = *(const float4*)(Abase + (size_t)t * rowstep * K);
            float4 bv = *(const float4*)(Bbase + (size_t)t * rowstep * K);
            uint32_t h0, l0, h1, l1;
            uint32_t off = (uint32_t)((lrow + t * rowstep) * GSTRIDE + lq * 8);
            split2(av.x, av.y, h0, l0); split2(av.z, av.w, h1, l1);
            *(uint2*)(stg + AH_OFF + off) = make_uint2(h0, h1);
            *(uint2*)(stg + AL_OFF + off) = make_uint2(l0, l1);
            split2(bv.x, bv.y, h0, l0); split2(bv.z, bv.w, h1, l1);
            *(uint2*)(stg + BH_OFF + off) = make_uint2(h0, h1);
            *(uint2*)(stg + BL_OFF + off) = make_uint2(l0, l1);
        }
    }
    __syncthreads();

    for (int c = 0; c < nchunk; ++c) {
        // ---- issue gmem loads for chunk c+1 ----
        float4 av[4], bv[4];
        const bool more = (c + 1 < nchunk);
        if (more) {
            const float* Ac = Abase + (size_t)(c + 1) * 32;
            const float* Bc = Bbase + (size_t)(c + 1) * 32;
#pragma unroll
            for (int t = 0; t < 4; ++t) {
                av[t] = *(const float4*)(Ac + (size_t)t * rowstep * K);
                bv[t] = *(const float4*)(Bc + (size_t)t * rowstep * K);
            }
        }

        // ---- compute chunk c from stage c&1 ----
        const uint32_t stg_u = sb + (uint32_t)(c & 1) * STAGE_SZ;
        const uint32_t a_base = stg_u + AH_OFF + (uint32_t)(wm * 64) * GSTRIDE + a_lane_off;
        const uint32_t al_base = a_base + (AL_OFF - AH_OFF);
        const uint32_t b_base = stg_u + BH_OFF + (uint32_t)(wn * 32) * GSTRIDE + b_lane_off;
        const uint32_t bl_base = b_base + (BL_OFF - BH_OFF);

#pragma unroll
        for (int ks = 0; ks < 2; ++ks) {
            uint32_t ah[4][4], al[4][4], bh[4][2], bl[4][2];
#pragma unroll
            for (int mt = 0; mt < 4; ++mt) {
                uint32_t ad = a_base + (uint32_t)(mt * 16) * GSTRIDE + (uint32_t)(ks * 32);
                ldm4(ad, ah[mt][0], ah[mt][1], ah[mt][2], ah[mt][3]);
                uint32_t ad2 = al_base + (uint32_t)(mt * 16) * GSTRIDE + (uint32_t)(ks * 32);
                ldm4(ad2, al[mt][0], al[mt][1], al[mt][2], al[mt][3]);
            }
#pragma unroll
            for (int np = 0; np < 2; ++np) {
                uint32_t bd = b_base + (uint32_t)(np * 16) * GSTRIDE + (uint32_t)(ks * 32);
                ldm4(bd, bh[np*2][0], bh[np*2][1], bh[np*2+1][0], bh[np*2+1][1]);
                uint32_t bd2 = bl_base + (uint32_t)(np * 16) * GSTRIDE + (uint32_t)(ks * 32);
                ldm4(bd2, bl[np*2][0], bl[np*2][1], bl[np*2+1][0], bl[np*2+1][1]);
            }
#pragma unroll
            for (int mt = 0; mt < 4; ++mt)
#pragma unroll
                for (int nt = 0; nt < 4; ++nt) {
                    mma16816(acc[mt][nt], ah[mt], bh[nt]);
                    mma16816(acc[mt][nt], al[mt], bh[nt]);
                    mma16816(acc[mt][nt], ah[mt], bl[nt]);
                }
        }

        // ---- store chunk c+1 into stage (c+1)&1 ----
        if (more) {
            char* stg = smem + ((c + 1) & 1) * STAGE_SZ;
#pragma unroll
            for (int t = 0; t < 4; ++t) {
                uint32_t h0, l0, h1, l1;
                uint32_t off = (uint32_t)((lrow + t * rowstep) * GSTRIDE + lq * 8);
                split2(av[t].x, av[t].y, h0, l0); split2(av[t].z, av[t].w, h1, l1);
                *(uint2*)(stg + AH_OFF + off) = make_uint2(h0, h1);
                *(uint2*)(stg + AL_OFF + off) = make_uint2(l0, l1);
                split2(bv[t].x, bv[t].y, h0, l0); split2(bv[t].z, bv[t].w, h1, l1);
                *(uint2*)(stg + BH_OFF + off) = make_uint2(h0, h1);
                *(uint2*)(stg + BL_OFF + off) = make_uint2(l0, l1);
            }
        }
        __syncthreads();
    }

    // ---- epilogue ----
    const int erow = m0 + wm * 64 + (lane >> 2);
    const int ecol = n0 + wn * 32 + (lane & 3) * 2;
#pragma unroll
    for (int mt = 0; mt < 4; ++mt) {
#pragma unroll
        for (int nt = 0; nt < 4; ++nt) {
            const int r0 = erow + mt * 16;
            const int cc = ecol + nt * 8;
            float2 v0 = make_float2(acc[mt][nt][0], acc[mt][nt][1]);
            float2 v1 = make_float2(acc[mt][nt][2], acc[mt][nt][3]);
            if (BIAS) {
                float2 bb = *(const float2*)(bias + cc);
                v0.x += bb.x; v0.y += bb.y; v1.x += bb.x; v1.y += bb.y;
            }
            if (RELU) {
                v0.x = fmaxf(v0.x, 0.f); v0.y = fmaxf(v0.y, 0.f);
                v1.x = fmaxf(v1.x, 0.f); v1.y = fmaxf(v1.y, 0.f);
            }
            if (RES) {
                float2 r4 = *(const float2*)(res + (size_t)r0 * N + cc);
                v0.x += r4.x; v0.y += r4.y;
                float2 r5 = *(const float2*)(res + (size_t)(r0 + 8) * N + cc);
                v1.x += r5.x; v1.y += r5.y;
            }
            *(float2*)(C + (size_t)r0 * N + cc) = v0;
            *(float2*)(C + (size_t)(r0 + 8) * N + cc) = v1;
        }
    }
}

// ---------------- conv_in ----------------------------------------------------------
__global__ void conv_in_kernel(const float* __restrict__ x,
                               const float* __restrict__ w,
                               const float* __restrict__ b,
                               float* __restrict__ h)
{
    int idx = blockIdx.x * blockDim.x + threadIdx.x;
    if (idx >= SEQ * DMODEL) return;
    int d = idx & (DMODEL - 1);
    int l = idx >> 10;
    float acc = b[d];
#pragma unroll
    for (int c = 0; c < CIN; ++c) {
#pragma unroll
        for (int t = 0; t < KW; ++t) {
            int lt = l + t - (KW - 1);
            if (lt >= 0) acc += w[(d * CIN + c) * KW + t] * x[c * SEQ + lt];
        }
    }
    h[idx] = fmaxf(acc, 0.0f);
}

// ---------------- conv_out ---------------------------------------------------------
__global__ void conv_out_kernel(const float* __restrict__ xb,
                                const float* __restrict__ w,
                                const float* __restrict__ b,
                                float* __restrict__ out)
{
    int l  = blockIdx.x;
    int co = blockIdx.y;
    float acc = 0.0f;
    for (int d = threadIdx.x; d < DMODEL; d += 128) {
        const float* wp = w + (size_t)(co * DMODEL + d) * KW;
#pragma unroll
        for (int t = 0; t < KW; ++t) {
            int lt = l + t - (KW - 1);
            if (lt >= 0) acc += wp[t] * xb[(size_t)lt * DMODEL + d];
        }
    }
#pragma unroll
    for (int s = 16; s >= 1; s >>= 1) acc += __shfl_xor_sync(0xffffffffu, acc, s);
    __shared__ float red[4];
    if ((threadIdx.x & 31) == 0) red[threadIdx.x >> 5] = acc;
    __syncthreads();
    if (threadIdx.x == 0)
        out[co * SEQ + l] = red[0] + red[1] + red[2] + red[3] + b[co];
}

// ---------------- RMSNorm ----------------------------------------------------------
__global__ void __launch_bounds__(256) rmsnorm_kernel(const float* __restrict__ x,
                                                      const float* __restrict__ w,
                                                      const float* __restrict__ b,
                                                      float* __restrict__ y)
{
    int l = blockIdx.x;
    const float* xr = x + (size_t)l * DMODEL;
    float ss = 0.0f;
    for (int i = threadIdx.x; i < DMODEL; i += 256) { float v = xr[i]; ss += v * v; }
#pragma unroll
    for (int s = 16; s >= 1; s >>= 1) ss += __shfl_xor_sync(0xffffffffu, ss, s);
    __shared__ float red[8];
    __shared__ float sinv;
    if ((threadIdx.x & 31) == 0) red[threadIdx.x >> 5] = ss;
    __syncthreads();
    if (threadIdx.x == 0) {
        float t = 0.0f;
#pragma unroll
        for (int i = 0; i < 8; ++i) t += red[i];
        sinv = rsqrtf(t * (1.0f / DMODEL) + 1e-5f);
    }
    __syncthreads();
    float inv = sinv;
    float* yr = y + (size_t)l * DMODEL;
    for (int i = threadIdx.x; i < DMODEL; i += 256)
        yr[i] = xr[i] * inv * w[i] + b[i];
}

// ---------------- RoPE -------------------------------------------------------------
__global__ void rope_kernel(float* __restrict__ q, float* __restrict__ k)
{
    int idx = blockIdx.x * blockDim.x + threadIdx.x;
    if (idx >= SEQ * NHEADS * (HD / 2)) return;
    int j = idx & 31;
    int h = (idx >> 5) & (NHEADS - 1);
    int l = idx >> 9;
    float inv_freq = exp2f(-(float)j * (13.287712379549449f / 32.0f));
    float ang = (float)l * inv_freq;
    float s, c;
    sincosf(ang, &s, &c);
    int base = l * DMODEL + h * HD + j;
    float q1 = q[base], q2 = q[base + 32];
    q[base]      = q1 * c - q2 * s;
    q[base + 32] = q2 * c + q1 * s;
    float k1 = k[base], k2 = k[base + 32];
    k[base]      = k1 * c - k2 * s;
    k[base + 32] = k2 * c + k1 * s;
}

// ---------------- Flash attention (fp32, 64x64 tiles) ------------------------------
#define ATTN_PAD 65
#define ATTN_SMEM (4 * 64 * ATTN_PAD * (int)sizeof(float))

__global__ void __launch_bounds__(256) attn_kernel(const float* __restrict__ Q,
                                                   const float* __restrict__ Kt,
                                                   const float* __restrict__ V,
                                                   float* __restrict__ O)
{
    extern __shared__ float sm[];
    float* Qs = sm;
    float* Ks = sm + 64 * ATTN_PAD;
    float* Vs = sm + 2 * 64 * ATTN_PAD;
    float* Ps = sm + 3 * 64 * ATTN_PAD;

    const int h  = blockIdx.y;
    const int qt = blockIdx.x;
    const int q0 = qt * 64;
    const int tid = threadIdx.x;
    const int tx = tid & 15;
    const int ty = tid >> 4;

    for (int i = tid; i < 64 * 64; i += 256) {
        int r = i >> 6, c = i & 63;
        Qs[r * ATTN_PAD + c] = Q[(size_t)(q0 + r) * DMODEL + h * HD + c];
    }

    float m_i[4], l_i[4], oacc[4][4];
#pragma unroll
    for (int r = 0; r < 4; ++r) {
        m_i[r] = -INFINITY; l_i[r] = 0.0f;
#pragma unroll
        for (int c = 0; c < 4; ++c) oacc[r][c] = 0.0f;
    }

    for (int jt = 0; jt <= qt; ++jt) {
        const int k0 = jt * 64;
        __syncthreads();
        for (int i = tid; i < 64 * 64; i += 256) {
            int r = i >> 6, c = i & 63;
            Ks[r * ATTN_PAD + c] = Kt[(size_t)(k0 + r) * DMODEL + h * HD + c];
            Vs[r * ATTN_PAD + c] = V [(size_t)(k0 + r) * DMODEL + h * HD + c];
        }
        __syncthreads();

        float s[4][4];
#pragma unroll
        for (int r = 0; r < 4; ++r)
#pragma unroll
            for (int c = 0; c < 4; ++c) s[r][c] = 0.0f;

        for (int d = 0; d < HD; ++d) {
            float qv[4], kv[4];
#pragma unroll
            for (int r = 0; r < 4; ++r) qv[r] = Qs[(ty * 4 + r) * ATTN_PAD + d];
#pragma unroll
            for (int c = 0; c < 4; ++c) kv[c] = Ks[(tx * 4 + c) * ATTN_PAD + d];
#pragma unroll
            for (int r = 0; r < 4; ++r)
#pragma unroll
                for (int c = 0; c < 4; ++c) s[r][c] += qv[r] * kv[c];
        }

        const bool diag = (jt == qt);
#pragma unroll
        for (int r = 0; r < 4; ++r) {
            const int qi = q0 + ty * 4 + r;
            float rowmax = -INFINITY;
#pragma unroll
            for (int c = 0; c < 4; ++c) {
                s[r][c] *= 0.125f;
                if (diag) { int ki = k0 + tx * 4 + c; if (ki > qi) s[r][c] = -INFINITY; }
                rowmax = fmaxf(rowmax, s[r][c]);
            }
#pragma unroll
            for (int w = 8; w >= 1; w >>= 1)
                rowmax = fmaxf(rowmax, __shfl_xor_sync(0xffffffffu, rowmax, w));
            float mnew  = fmaxf(m_i[r], rowmax);
            float alpha = expf(m_i[r] - mnew);
            m_i[r] = mnew;
            float rsum = 0.0f;
#pragma unroll
            for (int c = 0; c < 4; ++c) {
                float p = expf(s[r][c] - mnew);
                s[r][c] = p;
                rsum += p;
            }
#pragma unroll
            for (int w = 8; w >= 1; w >>= 1)
                rsum += __shfl_xor_sync(0xffffffffu, rsum, w);
            l_i[r] = l_i[r] * alpha + rsum;
#pragma unroll
            for (int c = 0; c < 4; ++c) {
                oacc[r][c] *= alpha;
                Ps[(ty * 4 + r) * ATTN_PAD + tx * 4 + c] = s[r][c];
            }
        }
        __syncthreads();

        for (int j = 0; j < 64; ++j) {
            float pv[4], vv[4];
#pragma unroll
            for (int r = 0; r < 4; ++r) pv[r] = Ps[(ty * 4 + r) * ATTN_PAD + j];
#pragma unroll
            for (int c = 0; c < 4; ++c) vv[c] = Vs[j * ATTN_PAD + tx * 4 + c];
#pragma unroll
            for (int r = 0; r < 4; ++r)
#pragma unroll
                for (int c = 0; c < 4; ++c) oacc[r][c] += pv[r] * vv[c];
        }
    }

#pragma unroll
    for (int r = 0; r < 4; ++r) {
        float invl = 1.0f / l_i[r];
#pragma unroll
        for (int c = 0; c < 4; ++c)
            O[(size_t)(q0 + ty * 4 + r) * DMODEL + h * HD + tx * 4 + c] = oacc[r][c] * invl;
    }
}

// ---------------- host launcher ----------------------------------------------------
extern "C" void kernel_launch(void* const* d_in, const int* in_sizes, int n_in,
                              void* d_out, int out_size)
{
    const float* x_in       = (const float*)d_in[0];
    const float* conv_in_w  = (const float*)d_in[1];
    const float* conv_in_b  = (const float*)d_in[2];
    const float* ln1_w      = (const float*)d_in[3];
    const float* ln1_b      = (const float*)d_in[4];
    const float* wq         = (const float*)d_in[5];
    const float* wk         = (const float*)d_in[6];
    const float* wv         = (const float*)d_in[7];
    const float* wo         = (const float*)d_in[8];
    const float* ln2_w      = (const float*)d_in[9];
    const float* ln2_b      = (const float*)d_in[10];
    const float* w1         = (const float*)d_in[11];
    const float* b1         = (const float*)d_in[12];
    const float* w2         = (const float*)d_in[13];
    const float* b2         = (const float*)d_in[14];
    const float* w3         = (const float*)d_in[15];
    const float* b3         = (const float*)d_in[16];
    const float* conv_out_w = (const float*)d_in[17];
    const float* conv_out_b = (const float*)d_in[18];
    float* out = (float*)d_out;

    float *px, *phn, *pq, *pk, *pv, *po, *ph1, *ph2;
    cudaGetSymbolAddress((void**)&px,  g_x);
    cudaGetSymbolAddress((void**)&phn, g_hn);
    cudaGetSymbolAddress((void**)&pq,  g_q);
    cudaGetSymbolAddress((void**)&pk,  g_k);
    cudaGetSymbolAddress((void**)&pv,  g_v);
    cudaGetSymbolAddress((void**)&po,  g_o);
    cudaGetSymbolAddress((void**)&ph1, g_h1);
    cudaGetSymbolAddress((void**)&ph2, g_h2);

    cudaFuncSetAttribute(attn_kernel, cudaFuncAttributeMaxDynamicSharedMemorySize, ATTN_SMEM);
    cudaFuncSetAttribute(gemm_mma<false, false, false>, cudaFuncAttributeMaxDynamicSharedMemorySize, GSMEM_TOTAL);
    cudaFuncSetAttribute(gemm_mma<false, false, true>,  cudaFuncAttributeMaxDynamicSharedMemorySize, GSMEM_TOTAL);
    cudaFuncSetAttribute(gemm_mma<true, true, false>,   cudaFuncAttributeMaxDynamicSharedMemorySize, GSMEM_TOTAL);
    cudaFuncSetAttribute(gemm_mma<true, false, true>,   cudaFuncAttributeMaxDynamicSharedMemorySize, GSMEM_TOTAL);

    conv_in_kernel<<<(SEQ * DMODEL) / 256, 256>>>(x_in, conv_in_w, conv_in_b, px);

    const dim3 gD(DMODEL / 128, SEQ / 128);
    const dim3 gF(DFF / 128,    SEQ / 128);

    for (int i = 0; i < NLAYERS; ++i) {
        rmsnorm_kernel<<<SEQ, 256>>>(px, ln1_w + i * DMODEL, ln1_b + i * DMODEL, phn);

        gemm_mma<false, false, false><<<gD, 256, GSMEM_TOTAL>>>(DMODEL, DMODEL, phn,
            wq + (size_t)i * DMODEL * DMODEL, nullptr, nullptr, pq);
        gemm_mma<false, false, false><<<gD, 256, GSMEM_TOTAL>>>(DMODEL, DMODEL, phn,
            wk + (size_t)i * DMODEL * DMODEL, nullptr, nullptr, pk);
        gemm_mma<false, false, false><<<gD, 256, GSMEM_TOTAL>>>(DMODEL, DMODEL, phn,
            wv + (size_t)i * DMODEL * DMODEL, nullptr, nullptr, pv);

        rope_kernel<<<(SEQ * NHEADS * (HD / 2)) / 256, 256>>>(pq, pk);

        attn_kernel<<<dim3(SEQ / 64, NHEADS), 256, ATTN_SMEM>>>(pq, pk, pv, po);

        gemm_mma<false, false, true><<<gD, 256, GSMEM_TOTAL>>>(DMODEL, DMODEL, po,
            wo + (size_t)i * DMODEL * DMODEL, nullptr, px, px);

        rmsnorm_kernel<<<SEQ, 256>>>(px, ln2_w + i * DMODEL, ln2_b + i * DMODEL, phn);

        gemm_mma<true, true, false><<<gF, 256, GSMEM_TOTAL>>>(DMODEL, DFF, phn,
            w1 + (size_t)i * DFF * DMODEL, b1 + (size_t)i * DFF, nullptr, ph1);
        gemm_mma<true, true, false><<<gF, 256, GSMEM_TOTAL>>>(DFF, DFF, ph1,
            w2 + (size_t)i * DFF * DFF, b2 + (size_t)i * DFF, nullptr, ph2);
        gemm_mma<true, false, true><<<gD, 256, GSMEM_TOTAL>>>(DFF, DMODEL, ph2,
            w3 + (size_t)i * DMODEL * DFF, b3 + (size_t)i * DMODEL, px, px);
    }

    conv_out_kernel<<<dim3(SEQ, COUT), 128>>>(px, conv_out_w, conv_out_b, out);
}